// round 16
// baseline (speedup 1.0000x reference)
#include <cuda_runtime.h>
#include <cuda_fp16.h>
#include <cstdint>
#include <math.h>

#define NTOK 4096
#define HDIM 768
#define FDIM 3072
#define ENUM 6
#define EBKT 4096                    // per-expert bucket capacity (max tokens)

// fp16 tiles: A 128x32 halfs, B 128x32 halfs, row pitch 40 halfs (80B, 16B-aligned)
#define ROWP 40
#define TILE_H (128 * ROWP)          // halfs per tile
#define STG_H  (2 * TILE_H)          // A + B
#define N_ST 5
#define SMEM_REQ (N_ST * STG_H * 2)  // 102400 B -> 2 CTAs/SM (204.8KB)

#define GRID_DEP_WAIT() asm volatile("griddepcontrol.wait;" ::: "memory")

// ---------------- device scratch (no allocations allowed) ----------------
__device__ int    g_counts[ENUM];
__device__ int    g_slot_tok[ENUM * EBKT];
__device__ float  g_slot_w[ENUM * EBKT];
__device__ __half g_xh[(size_t)NTOK * HDIM];                 // fp16 x
__device__ __half g_hmidh[(size_t)ENUM * EBKT * FDIM];       // fp16 mid acts (bucketed)
__device__ __half g_w1h[(size_t)ENUM * FDIM * HDIM];         // w1^T fp16 [E][F][H] = [N][K]
__device__ __half g_w2h[(size_t)ENUM * HDIM * FDIM];         // w2^T fp16 [E][H][F] = [N][K]

// ---------------- helpers ----------------
__device__ __forceinline__ float gelu_exact(float x) {
    return 0.5f * x * (1.0f + erff(x * 0.7071067811865476f));
}
__device__ __forceinline__ uint32_t smem_u32(const void* p) {
    uint32_t a;
    asm("{ .reg .u64 t; cvta.to.shared.u64 t, %1; cvt.u32.u64 %0, t; }" : "=r"(a) : "l"(p));
    return a;
}
__device__ __forceinline__ void cp16(uint32_t dst, const void* src, bool pred) {
    int sz = pred ? 16 : 0;   // src-size 0 => zero-fill
    asm volatile("cp.async.cg.shared.global [%0], [%1], 16, %2;"
                 :: "r"(dst), "l"(src), "r"(sz) : "memory");
}
#define CP_COMMIT() asm volatile("cp.async.commit_group;" ::: "memory")
#define CP_WAIT(n)  asm volatile("cp.async.wait_group %0;" :: "n"(n) : "memory")

__device__ __forceinline__ void ldm_x4(uint32_t* r, uint32_t addr) {
    asm volatile("ldmatrix.sync.aligned.m8n8.x4.shared.b16 {%0,%1,%2,%3}, [%4];"
                 : "=r"(r[0]), "=r"(r[1]), "=r"(r[2]), "=r"(r[3]) : "r"(addr));
}

__device__ __forceinline__ void mma_f16(float* c, const uint32_t* a, const uint32_t* b) {
    asm volatile(
        "mma.sync.aligned.m16n8k16.row.col.f32.f16.f16.f32 "
        "{%0,%1,%2,%3}, {%4,%5,%6,%7}, {%8,%9}, {%0,%1,%2,%3};\n"
        : "+f"(c[0]), "+f"(c[1]), "+f"(c[2]), "+f"(c[3])
        : "r"(a[0]), "r"(a[1]), "r"(a[2]), "r"(a[3]), "r"(b[0]), "r"(b[1]));
}

__device__ __forceinline__ void red_v2(float* ptr, float v0, float v1) {
    asm volatile("red.global.add.v2.f32 [%0], {%1, %2};"
                 :: "l"(ptr), "f"(v0), "f"(v1) : "memory");
}

// ---------------- merged weight prep (+counter zero rides launch #1) ----------
// z in [0,6):  w1 [E][H][F] -> g_w1h [E][F][H]
// z in [6,12): w2 [E][F][H] -> g_w2h [E][H][F]
__global__ void prep_w_k(const float* __restrict__ w1, const float* __restrict__ w2) {
    if (blockIdx.x == 0 && blockIdx.y == 0 && blockIdx.z == 0 && threadIdx.x < ENUM)
        g_counts[threadIdx.x] = 0;
    __shared__ float t[32][33];
    const int z = blockIdx.z;
    const bool is1 = (z < ENUM);
    const int e = is1 ? z : z - ENUM;
    const int R = is1 ? HDIM : FDIM;
    const int C = is1 ? FDIM : HDIM;
    const int c0 = (is1 ? blockIdx.x : blockIdx.y) * 32;
    const int r0 = (is1 ? blockIdx.y : blockIdx.x) * 32;
    const float* s = (is1 ? w1 : w2) + (size_t)e * HDIM * FDIM;
    __half* d = (is1 ? g_w1h : g_w2h) + (size_t)e * HDIM * FDIM;
    const int tx = threadIdx.x & 31, ty = threadIdx.x >> 5;
#pragma unroll
    for (int i = 0; i < 32; i += 8)
        t[ty + i][tx] = s[(size_t)(r0 + ty + i) * C + c0 + tx];
    __syncthreads();
#pragma unroll
    for (int i = 0; i < 32; i += 8)
        d[(size_t)(c0 + ty + i) * R + r0 + tx] = __float2half_rn(t[tx][ty + i]);
}

// ---------------- gate: zero out rows + x->fp16 + top-2 + direct scatter ------
__global__ void gate_kernel(const float* __restrict__ x,
                            const float* __restrict__ gw,
                            const float* __restrict__ gb,
                            float* __restrict__ out) {
    const int tid  = threadIdx.x;
    const int warp = tid >> 5;
    const int lane = tid & 31;
    const int tokbase = blockIdx.x * 8;
    const int tok = tokbase + warp;

    // zero the 8 output rows owned by this block (8*768 floats = 1536 float4)
    float4* oz = (float4*)(out + (size_t)tokbase * HDIM);
#pragma unroll
    for (int i = 0; i < 6; ++i)
        oz[tid + 256 * i] = make_float4(0.f, 0.f, 0.f, 0.f);

    float acc[ENUM];
#pragma unroll
    for (int e = 0; e < ENUM; ++e) acc[e] = 0.0f;

    const float* xr = x + (size_t)tok * HDIM;
    __half* xh = g_xh + (size_t)tok * HDIM;
    for (int h = lane; h < HDIM; h += 32) {
        float xv = xr[h];
        xh[h] = __float2half_rn(xv);            // fused x -> fp16 conversion
#pragma unroll
        for (int e = 0; e < ENUM; ++e) acc[e] += xv * gw[h * ENUM + e];
    }
#pragma unroll
    for (int e = 0; e < ENUM; ++e) {
#pragma unroll
        for (int off = 16; off > 0; off >>= 1)
            acc[e] += __shfl_xor_sync(0xffffffffu, acc[e], off);
    }

    GRID_DEP_WAIT();   // prep_w must have zeroed g_counts before the scatter

    if (lane == 0) {
        float best = -1e30f, sec = -1e30f;
        int bi = 0, si = 0;
#pragma unroll
        for (int e = 0; e < ENUM; ++e) {
            float s = acc[e] + gb[e];
            if (s > best) { sec = best; si = bi; best = s; bi = e; }
            else if (s > sec) { sec = s; si = e; }
        }
        float r = expf(sec - best);
        float inv = 1.0f / (1.0f + r);
        int p0 = atomicAdd(&g_counts[bi], 1);
        g_slot_tok[bi * EBKT + p0] = tok;
        g_slot_w[bi * EBKT + p0]   = inv;
        int p1 = atomicAdd(&g_counts[si], 1);
        g_slot_tok[si * EBKT + p1] = tok;
        g_slot_w[si * EBKT + p1]   = r * inv;
    }
}

// ---------------- grouped GEMM (fp16 mma + ldmatrix), BK=32, 5-stage,
//                  TWO k-tiles per barrier, register-pipelined fragments ----
// PHASE 1 (KSPLIT=1): hmidh = half(gelu(gather(xh) @ w1h^T + b1))
// PHASE 2 (KSPLIT=2): out += slot_w * (hmidh @ w2h^T [+ b2 if ks==0]) via red.v2
template <int PHASE, int KSPLIT>
__global__ void __launch_bounds__(256, 2) moe_gemm(const float* __restrict__ bias,
                                                   float* __restrict__ out) {
    constexpr int KTOT = (PHASE == 1) ? HDIM : FDIM;
    constexpr int KDIM = KTOT / KSPLIT;
    constexpr int NN   = (PHASE == 1) ? FDIM : HDIM;
    constexpr int KT   = KDIM / 32;          // 24 (phase1) / 48 (phase2) — even

    const int e    = blockIdx.z / KSPLIT;
    const int ks   = blockIdx.z % KSPLIT;
    const int kb   = ks * KDIM;
    const int base = e * EBKT;
    const int m0   = blockIdx.y * 128;
    const int n0   = blockIdx.x * 128;

    const __half* Wh = ((PHASE == 1) ? g_w1h : g_w2h) + (size_t)e * (size_t)NN * KTOT;

    extern __shared__ __half Sh[];   // [N_ST][A 128*ROWP | B 128*ROWP]
    const uint32_t sb = smem_u32(Sh);

    const int tid = threadIdx.x, wid = tid >> 5, lane = tid & 31;

    // cp.async mapping: thread -> (row = tid>>1, 32B half-row chunk = tid&1)
    const int crow = tid >> 1;
    const int coff = (tid & 1) * 16;      // halfs offset within row

    const __half* bptr = Wh + (size_t)(n0 + crow) * KTOT + kb + coff;
    const uint32_t sdst = (uint32_t)(crow * ROWP + coff) * 2;   // bytes within tile

    auto issueB = [&](int b, int k0) {
        uint32_t b_s = sb + (uint32_t)b * STG_H * 2 + TILE_H * 2 + sdst;
        cp16(b_s,      bptr + k0, true);
        cp16(b_s + 16, bptr + k0 + 8, true);
    };

    // ---- PDL pre-sync: weight prefetch (weights are >=2 kernels upstream) ----
    issueB(0, 0);  CP_COMMIT();
    issueB(1, 32); CP_COMMIT();
    issueB(2, 64); CP_COMMIT();

    GRID_DEP_WAIT();   // predecessor (gate / gemm1) complete: counts/slots/hmid visible

    const int cnt = g_counts[e];
    if (m0 >= cnt) { CP_WAIT(0); return; }

    const __half* aptr;                    // A row source (gathered / contiguous)
    {
        int m = m0 + crow;
        if (m < cnt) {
            if (PHASE == 1) aptr = g_xh + (size_t)g_slot_tok[base + m] * HDIM + kb + coff;
            else            aptr = g_hmidh + (size_t)(base + m) * FDIM + kb + coff;
        } else aptr = nullptr;
    }
    auto issueA = [&](int b, int k0) {
        uint32_t a_s = sb + (uint32_t)b * STG_H * 2 + sdst;
        cp16(a_s,      aptr ? (aptr + k0)     : (const __half*)Wh, aptr != nullptr);
        cp16(a_s + 16, aptr ? (aptr + k0 + 8) : (const __half*)Wh, aptr != nullptr);
    };
    auto issue = [&](int b, int k0) { issueA(b, k0); issueB(b, k0); };

    // finish prologue: A for tiles 0,1,2 (groups: B0,B1,B2,A0,A1,A2)
    issueA(0, 0);  CP_COMMIT();
    issueA(1, 32); CP_COMMIT();
    issueA(2, 64); CP_COMMIT();

    const int wm = (wid >> 2) * 64;
    const int wn = (wid & 3) * 32;
    const int g = lane >> 2, t = lane & 3;

    // ldmatrix per-lane fragment addresses (byte offsets within a stage)
    uint32_t offA[4];
#pragma unroll
    for (int mf = 0; mf < 4; ++mf)
        offA[mf] = (uint32_t)((wm + mf * 16 + (lane & 15)) * ROWP) * 2
                 + ((lane & 16) ? 16u : 0u);
    uint32_t offB[2];
#pragma unroll
    for (int j = 0; j < 2; ++j)
        offB[j] = (uint32_t)(TILE_H + (wn + j * 16 + (lane & 7) + ((lane & 16) ? 8 : 0)) * ROWP) * 2
                + ((lane & 8) ? 16u : 0u);

    float acc[4][4][4];
#pragma unroll
    for (int mf = 0; mf < 4; ++mf)
#pragma unroll
        for (int nf = 0; nf < 4; ++nf)
#pragma unroll
            for (int c = 0; c < 4; ++c) acc[mf][nf][c] = 0.0f;

    // register-pipelined fragments: af reloaded in-place after last use,
    // bf double-buffered by step parity.
    uint32_t af[4][4];
    uint32_t bf[2][2][4];

    // mainloop: 2 tiles (kt, kt+1) per barrier = 4 k16-steps, 5-stage rotation
    int s0 = 0;
    for (int jt = 0; jt < KT / 2; ++jt) {
        const int kt = 2 * jt;
        CP_WAIT(1);                    // tiles 0..kt+1 landed
        __syncthreads();               // + all warps done with tiles kt-2,kt-1

        int s3 = s0 + 3; if (s3 >= N_ST) s3 -= N_ST;   // stage of tile kt-2: free
        int s4 = s0 + 4; if (s4 >= N_ST) s4 -= N_ST;   // stage of tile kt-1: free
        if (kt + 3 < KT) issue(s3, (kt + 3) * 32);
        CP_COMMIT();
        if (kt + 4 < KT) issue(s4, (kt + 4) * 32);
        CP_COMMIT();

        int s1 = s0 + 1; if (s1 >= N_ST) s1 -= N_ST;
        const uint32_t stb[2] = { sb + (uint32_t)s0 * STG_H * 2,
                                  sb + (uint32_t)s1 * STG_H * 2 };

        // prime step 0 fragments (only this load chain pays full LDS latency)
#pragma unroll
        for (int mf = 0; mf < 4; ++mf) ldm_x4(af[mf], stb[0] + offA[mf]);
        ldm_x4(bf[0][0], stb[0] + offB[0]);
        ldm_x4(bf[0][1], stb[0] + offB[1]);

        // steps u: (stage u>>1, koff (u&1)*32)
#pragma unroll
        for (int u = 0; u < 4; ++u) {
            const int cur = u & 1;
            if (u < 3) {
                const uint32_t stb_n = stb[(u + 1) >> 1];
                const uint32_t ko_n = (uint32_t)(((u + 1) & 1) * 32);
                ldm_x4(bf[cur ^ 1][0], stb_n + offB[0] + ko_n);
                ldm_x4(bf[cur ^ 1][1], stb_n + offB[1] + ko_n);
#pragma unroll
                for (int mf = 0; mf < 4; ++mf) {
                    mma_f16(acc[mf][0], af[mf], &bf[cur][0][0]);
                    mma_f16(acc[mf][1], af[mf], &bf[cur][0][2]);
                    mma_f16(acc[mf][2], af[mf], &bf[cur][1][0]);
                    mma_f16(acc[mf][3], af[mf], &bf[cur][1][2]);
                    ldm_x4(af[mf], stb_n + offA[mf] + ko_n);  // WAR-safe reload
                }
            } else {
#pragma unroll
                for (int mf = 0; mf < 4; ++mf) {
                    mma_f16(acc[mf][0], af[mf], &bf[cur][0][0]);
                    mma_f16(acc[mf][1], af[mf], &bf[cur][0][2]);
                    mma_f16(acc[mf][2], af[mf], &bf[cur][1][0]);
                    mma_f16(acc[mf][3], af[mf], &bf[cur][1][2]);
                }
            }
        }

        s0 += 2; if (s0 >= N_ST) s0 -= N_ST;
    }

    // -------- epilogue --------
    const float* bv = bias + (size_t)e * NN;
    const float bscale = (ks == 0) ? 1.0f : 0.0f;   // bias once per K-split group
#pragma unroll
    for (int mf = 0; mf < 4; ++mf) {
        int rl = wm + mf * 16 + g;
#pragma unroll
        for (int nf = 0; nf < 4; ++nf) {
            int col = n0 + wn + nf * 8 + 2 * t;
            float bb0 = bv[col] * bscale, bb1 = bv[col + 1] * bscale;
#pragma unroll
            for (int half = 0; half < 2; ++half) {
                int mrow = m0 + rl + half * 8;
                if (mrow >= cnt) continue;
                float v0 = acc[mf][nf][half * 2 + 0] + bb0;
                float v1 = acc[mf][nf][half * 2 + 1] + bb1;
                if (PHASE == 1) {
                    size_t o = (size_t)(base + mrow) * FDIM + col;
                    *(__half2*)&g_hmidh[o] =
                        __float22half2_rn(make_float2(gelu_exact(v0), gelu_exact(v1)));
                } else {
                    int slot = base + mrow;
                    int tok = g_slot_tok[slot];
                    float w = g_slot_w[slot];
                    red_v2(&out[(size_t)tok * HDIM + col], w * v0, w * v1);
                }
            }
        }
    }
}

// ---------------- launch (PDL chain) ----------------
template <typename... Args>
static void launch_pdl(void (*k)(Args...), dim3 grid, dim3 block, size_t smem,
                       Args... args) {
    cudaLaunchAttribute attr[1];
    attr[0].id = cudaLaunchAttributeProgrammaticStreamSerialization;
    attr[0].val.programmaticStreamSerializationAllowed = 1;
    cudaLaunchConfig_t cfg = {};
    cfg.gridDim = grid;
    cfg.blockDim = block;
    cfg.dynamicSmemBytes = smem;
    cfg.attrs = attr;
    cfg.numAttrs = 1;
    cudaLaunchKernelEx(&cfg, k, args...);
}

extern "C" void kernel_launch(void* const* d_in, const int* in_sizes, int n_in,
                              void* d_out, int out_size) {
    const float* x  = (const float*)d_in[0];
    const float* gw = (const float*)d_in[1];
    const float* gb = (const float*)d_in[2];
    const float* w1 = (const float*)d_in[3];
    const float* b1 = (const float*)d_in[4];
    const float* w2 = (const float*)d_in[5];
    const float* b2 = (const float*)d_in[6];
    float* out = (float*)d_out;

    cudaFuncSetAttribute(moe_gemm<1, 1>, cudaFuncAttributeMaxDynamicSharedMemorySize, SMEM_REQ);
    cudaFuncSetAttribute(moe_gemm<2, 2>, cudaFuncAttributeMaxDynamicSharedMemorySize, SMEM_REQ);

    prep_w_k<<<dim3(FDIM / 32, HDIM / 32, 2 * ENUM), 256>>>(w1, w2);
    launch_pdl(gate_kernel, dim3(NTOK / 8), dim3(256), 0, x, gw, gb, out);
    launch_pdl(moe_gemm<1, 1>, dim3(FDIM / 128, EBKT / 128, ENUM), dim3(256),
               (size_t)SMEM_REQ, b1, (float*)nullptr);
    launch_pdl(moe_gemm<2, 2>, dim3(HDIM / 128, EBKT / 128, ENUM * 2), dim3(256),
               (size_t)SMEM_REQ, b2, out);
}

// round 17
// speedup vs baseline: 1.0089x; 1.0089x over previous
#include <cuda_runtime.h>
#include <cuda_fp16.h>
#include <cstdint>
#include <math.h>

#define NTOK 4096
#define HDIM 768
#define FDIM 3072
#define ENUM 6
#define EBKT 4096                    // per-expert bucket capacity (max tokens)

// fp16 tiles: A 128x32 halfs, B 128x32 halfs, row pitch 40 halfs (80B, 16B-aligned)
#define ROWP 40
#define TILE_H (128 * ROWP)          // halfs per tile
#define STG_H  (2 * TILE_H)          // A + B
#define N_ST 5
#define SMEM_REQ (N_ST * STG_H * 2)  // 102400 B -> 2 CTAs/SM (204.8KB)

#define GRID_DEP_WAIT() asm volatile("griddepcontrol.wait;" ::: "memory")

// ---------------- device scratch (no allocations allowed) ----------------
__device__ int    g_counts[ENUM];
__device__ int    g_done[ENUM];      // phase-1 CTA completion counters
__device__ int    g_slot_tok[ENUM * EBKT];
__device__ float  g_slot_w[ENUM * EBKT];
__device__ __half g_xh[(size_t)NTOK * HDIM];                 // fp16 x
__device__ __half g_hmidh[(size_t)ENUM * EBKT * FDIM];       // fp16 mid acts (bucketed)
__device__ __half g_w1h[(size_t)ENUM * FDIM * HDIM];         // w1^T fp16 [E][F][H] = [N][K]
__device__ __half g_w2h[(size_t)ENUM * HDIM * FDIM];         // w2^T fp16 [E][H][F] = [N][K]

// ---------------- helpers ----------------
__device__ __forceinline__ float gelu_exact(float x) {
    return 0.5f * x * (1.0f + erff(x * 0.7071067811865476f));
}
__device__ __forceinline__ uint32_t smem_u32(const void* p) {
    uint32_t a;
    asm("{ .reg .u64 t; cvta.to.shared.u64 t, %1; cvt.u32.u64 %0, t; }" : "=r"(a) : "l"(p));
    return a;
}
__device__ __forceinline__ void cp16(uint32_t dst, const void* src, bool pred) {
    int sz = pred ? 16 : 0;   // src-size 0 => zero-fill
    asm volatile("cp.async.cg.shared.global [%0], [%1], 16, %2;"
                 :: "r"(dst), "l"(src), "r"(sz) : "memory");
}
#define CP_COMMIT() asm volatile("cp.async.commit_group;" ::: "memory")
#define CP_WAIT(n)  asm volatile("cp.async.wait_group %0;" :: "n"(n) : "memory")

__device__ __forceinline__ void ldm_x4(uint32_t* r, uint32_t addr) {
    asm volatile("ldmatrix.sync.aligned.m8n8.x4.shared.b16 {%0,%1,%2,%3}, [%4];"
                 : "=r"(r[0]), "=r"(r[1]), "=r"(r[2]), "=r"(r[3]) : "r"(addr));
}

__device__ __forceinline__ void mma_f16(float* c, const uint32_t* a, const uint32_t* b) {
    asm volatile(
        "mma.sync.aligned.m16n8k16.row.col.f32.f16.f16.f32 "
        "{%0,%1,%2,%3}, {%4,%5,%6,%7}, {%8,%9}, {%0,%1,%2,%3};\n"
        : "+f"(c[0]), "+f"(c[1]), "+f"(c[2]), "+f"(c[3])
        : "r"(a[0]), "r"(a[1]), "r"(a[2]), "r"(a[3]), "r"(b[0]), "r"(b[1]));
}

__device__ __forceinline__ void red_v2(float* ptr, float v0, float v1) {
    asm volatile("red.global.add.v2.f32 [%0], {%1, %2};"
                 :: "l"(ptr), "f"(v0), "f"(v1) : "memory");
}

__device__ __forceinline__ int ld_acquire(const int* p) {
    int v;
    asm volatile("ld.acquire.gpu.global.b32 %0, [%1];" : "=r"(v) : "l"(p) : "memory");
    return v;
}

// ---------------- merged weight prep (+counter zero rides launch #1) ----------
// z in [0,6):  w1 [E][H][F] -> g_w1h [E][F][H]
// z in [6,12): w2 [E][F][H] -> g_w2h [E][H][F]
__global__ void prep_w_k(const float* __restrict__ w1, const float* __restrict__ w2) {
    if (blockIdx.x == 0 && blockIdx.y == 0 && blockIdx.z == 0 && threadIdx.x < ENUM) {
        g_counts[threadIdx.x] = 0;
        g_done[threadIdx.x] = 0;
    }
    __shared__ float t[32][33];
    const int z = blockIdx.z;
    const bool is1 = (z < ENUM);
    const int e = is1 ? z : z - ENUM;
    const int R = is1 ? HDIM : FDIM;
    const int C = is1 ? FDIM : HDIM;
    const int c0 = (is1 ? blockIdx.x : blockIdx.y) * 32;
    const int r0 = (is1 ? blockIdx.y : blockIdx.x) * 32;
    const float* s = (is1 ? w1 : w2) + (size_t)e * HDIM * FDIM;
    __half* d = (is1 ? g_w1h : g_w2h) + (size_t)e * HDIM * FDIM;
    const int tx = threadIdx.x & 31, ty = threadIdx.x >> 5;
#pragma unroll
    for (int i = 0; i < 32; i += 8)
        t[ty + i][tx] = s[(size_t)(r0 + ty + i) * C + c0 + tx];
    __syncthreads();
#pragma unroll
    for (int i = 0; i < 32; i += 8)
        d[(size_t)(c0 + ty + i) * R + r0 + tx] = __float2half_rn(t[tx][ty + i]);
}

// ---------------- gate: zero out rows + x->fp16 + top-2 + direct scatter ------
__global__ void gate_kernel(const float* __restrict__ x,
                            const float* __restrict__ gw,
                            const float* __restrict__ gb,
                            float* __restrict__ out) {
    const int tid  = threadIdx.x;
    const int warp = tid >> 5;
    const int lane = tid & 31;
    const int tokbase = blockIdx.x * 8;
    const int tok = tokbase + warp;

    // zero the 8 output rows owned by this block (8*768 floats = 1536 float4)
    float4* oz = (float4*)(out + (size_t)tokbase * HDIM);
#pragma unroll
    for (int i = 0; i < 6; ++i)
        oz[tid + 256 * i] = make_float4(0.f, 0.f, 0.f, 0.f);

    float acc[ENUM];
#pragma unroll
    for (int e = 0; e < ENUM; ++e) acc[e] = 0.0f;

    const float* xr = x + (size_t)tok * HDIM;
    __half* xh = g_xh + (size_t)tok * HDIM;
    for (int h = lane; h < HDIM; h += 32) {
        float xv = xr[h];
        xh[h] = __float2half_rn(xv);            // fused x -> fp16 conversion
#pragma unroll
        for (int e = 0; e < ENUM; ++e) acc[e] += xv * gw[h * ENUM + e];
    }
#pragma unroll
    for (int e = 0; e < ENUM; ++e) {
#pragma unroll
        for (int off = 16; off > 0; off >>= 1)
            acc[e] += __shfl_xor_sync(0xffffffffu, acc[e], off);
    }

    GRID_DEP_WAIT();   // prep_w must have zeroed g_counts before the scatter

    if (lane == 0) {
        float best = -1e30f, sec = -1e30f;
        int bi = 0, si = 0;
#pragma unroll
        for (int e = 0; e < ENUM; ++e) {
            float s = acc[e] + gb[e];
            if (s > best) { sec = best; si = bi; best = s; bi = e; }
            else if (s > sec) { sec = s; si = e; }
        }
        float r = expf(sec - best);
        float inv = 1.0f / (1.0f + r);
        int p0 = atomicAdd(&g_counts[bi], 1);
        g_slot_tok[bi * EBKT + p0] = tok;
        g_slot_w[bi * EBKT + p0]   = inv;
        int p1 = atomicAdd(&g_counts[si], 1);
        g_slot_tok[si * EBKT + p1] = tok;
        g_slot_w[si * EBKT + p1]   = r * inv;
    }
}

// ---------------- fused grouped GEMM body (fp16 mma + ldmatrix, BK=32,
//                  5-stage cp.async, 2 k-tiles/barrier, reg-pipelined frags) ----
// PHASE 1: hmidh[e] = half(gelu(gather(xh) @ w1h^T + b1)); done[e]++ per CTA
// PHASE 2: out += slot_w * (hmidh @ w2h^T [+ b2 if ks==0]) via red.v2
//          (waits on done[e] == expected before touching hmid)
template <int PHASE, int KSPLIT>
__device__ __forceinline__ void gemm_body(int e, int ks, int nx, int my,
                                          const float* __restrict__ bias,
                                          float* __restrict__ out) {
    constexpr int KTOT = (PHASE == 1) ? HDIM : FDIM;
    constexpr int KDIM = KTOT / KSPLIT;
    constexpr int NN   = (PHASE == 1) ? FDIM : HDIM;
    constexpr int KT   = KDIM / 32;          // 24 (both phases) — even

    const int kb   = ks * KDIM;
    const int base = e * EBKT;
    const int m0   = my * 128;
    const int n0   = nx * 128;

    const __half* Wh = ((PHASE == 1) ? g_w1h : g_w2h) + (size_t)e * (size_t)NN * KTOT;

    extern __shared__ __half Sh[];   // [N_ST][A 128*ROWP | B 128*ROWP]
    const uint32_t sb = smem_u32(Sh);

    const int tid = threadIdx.x, wid = tid >> 5, lane = tid & 31;

    // cp.async mapping: thread -> (row = tid>>1, 32B half-row chunk = tid&1)
    const int crow = tid >> 1;
    const int coff = (tid & 1) * 16;      // halfs offset within row

    const __half* bptr = Wh + (size_t)(n0 + crow) * KTOT + kb + coff;
    const uint32_t sdst = (uint32_t)(crow * ROWP + coff) * 2;   // bytes within tile

    auto issueB = [&](int b, int k0) {
        uint32_t b_s = sb + (uint32_t)b * STG_H * 2 + TILE_H * 2 + sdst;
        cp16(b_s,      bptr + k0, true);
        cp16(b_s + 16, bptr + k0 + 8, true);
    };

    // ---- PDL pre-sync: weight prefetch (weights are >=2 kernels upstream) ----
    issueB(0, 0);  CP_COMMIT();
    issueB(1, 32); CP_COMMIT();
    issueB(2, 64); CP_COMMIT();

    GRID_DEP_WAIT();   // gate complete: counts/slots/xh visible

    const int cnt = g_counts[e];
    if (m0 >= cnt) { CP_WAIT(0); return; }

    if (PHASE == 2) {
        // expert-granularity wait: all phase-1 CTAs of expert e retired
        const int expected = (FDIM / 128) * ((cnt + 127) >> 7);
        if (tid == 0) {
            while (ld_acquire(&g_done[e]) < expected) __nanosleep(64);
        }
        __syncthreads();   // broadcast acquire to all warps before A loads
    }

    const __half* aptr;                    // A row source (gathered / contiguous)
    {
        int m = m0 + crow;
        if (m < cnt) {
            if (PHASE == 1) aptr = g_xh + (size_t)g_slot_tok[base + m] * HDIM + kb + coff;
            else            aptr = g_hmidh + (size_t)(base + m) * FDIM + kb + coff;
        } else aptr = nullptr;
    }
    auto issueA = [&](int b, int k0) {
        uint32_t a_s = sb + (uint32_t)b * STG_H * 2 + sdst;
        cp16(a_s,      aptr ? (aptr + k0)     : (const __half*)Wh, aptr != nullptr);
        cp16(a_s + 16, aptr ? (aptr + k0 + 8) : (const __half*)Wh, aptr != nullptr);
    };
    auto issue = [&](int b, int k0) { issueA(b, k0); issueB(b, k0); };

    // finish prologue: A for tiles 0,1,2 (groups: B0,B1,B2,A0,A1,A2)
    issueA(0, 0);  CP_COMMIT();
    issueA(1, 32); CP_COMMIT();
    issueA(2, 64); CP_COMMIT();

    const int wm = (wid >> 2) * 64;
    const int wn = (wid & 3) * 32;
    const int g = lane >> 2, t = lane & 3;

    // ldmatrix per-lane fragment addresses (byte offsets within a stage)
    uint32_t offA[4];
#pragma unroll
    for (int mf = 0; mf < 4; ++mf)
        offA[mf] = (uint32_t)((wm + mf * 16 + (lane & 15)) * ROWP) * 2
                 + ((lane & 16) ? 16u : 0u);
    uint32_t offB[2];
#pragma unroll
    for (int j = 0; j < 2; ++j)
        offB[j] = (uint32_t)(TILE_H + (wn + j * 16 + (lane & 7) + ((lane & 16) ? 8 : 0)) * ROWP) * 2
                + ((lane & 8) ? 16u : 0u);

    float acc[4][4][4];
#pragma unroll
    for (int mf = 0; mf < 4; ++mf)
#pragma unroll
        for (int nf = 0; nf < 4; ++nf)
#pragma unroll
            for (int c = 0; c < 4; ++c) acc[mf][nf][c] = 0.0f;

    uint32_t af[4][4];
    uint32_t bf[2][2][4];

    int s0 = 0;
    for (int jt = 0; jt < KT / 2; ++jt) {
        const int kt = 2 * jt;
        CP_WAIT(1);                    // tiles 0..kt+1 landed
        __syncthreads();               // + all warps done with tiles kt-2,kt-1

        int s3 = s0 + 3; if (s3 >= N_ST) s3 -= N_ST;
        int s4 = s0 + 4; if (s4 >= N_ST) s4 -= N_ST;
        if (kt + 3 < KT) issue(s3, (kt + 3) * 32);
        CP_COMMIT();
        if (kt + 4 < KT) issue(s4, (kt + 4) * 32);
        CP_COMMIT();

        int s1 = s0 + 1; if (s1 >= N_ST) s1 -= N_ST;
        const uint32_t stb[2] = { sb + (uint32_t)s0 * STG_H * 2,
                                  sb + (uint32_t)s1 * STG_H * 2 };

        // prime step 0 fragments
#pragma unroll
        for (int mf = 0; mf < 4; ++mf) ldm_x4(af[mf], stb[0] + offA[mf]);
        ldm_x4(bf[0][0], stb[0] + offB[0]);
        ldm_x4(bf[0][1], stb[0] + offB[1]);

#pragma unroll
        for (int u = 0; u < 4; ++u) {
            const int cur = u & 1;
            if (u < 3) {
                const uint32_t stb_n = stb[(u + 1) >> 1];
                const uint32_t ko_n = (uint32_t)(((u + 1) & 1) * 32);
                ldm_x4(bf[cur ^ 1][0], stb_n + offB[0] + ko_n);
                ldm_x4(bf[cur ^ 1][1], stb_n + offB[1] + ko_n);
#pragma unroll
                for (int mf = 0; mf < 4; ++mf) {
                    mma_f16(acc[mf][0], af[mf], &bf[cur][0][0]);
                    mma_f16(acc[mf][1], af[mf], &bf[cur][0][2]);
                    mma_f16(acc[mf][2], af[mf], &bf[cur][1][0]);
                    mma_f16(acc[mf][3], af[mf], &bf[cur][1][2]);
                    ldm_x4(af[mf], stb_n + offA[mf] + ko_n);  // WAR-safe reload
                }
            } else {
#pragma unroll
                for (int mf = 0; mf < 4; ++mf) {
                    mma_f16(acc[mf][0], af[mf], &bf[cur][0][0]);
                    mma_f16(acc[mf][1], af[mf], &bf[cur][0][2]);
                    mma_f16(acc[mf][2], af[mf], &bf[cur][1][0]);
                    mma_f16(acc[mf][3], af[mf], &bf[cur][1][2]);
                }
            }
        }

        s0 += 2; if (s0 >= N_ST) s0 -= N_ST;
    }

    // -------- epilogue --------
    const float* bv = bias + (size_t)e * NN;
    const float bscale = (ks == 0) ? 1.0f : 0.0f;
#pragma unroll
    for (int mf = 0; mf < 4; ++mf) {
        int rl = wm + mf * 16 + g;
#pragma unroll
        for (int nf = 0; nf < 4; ++nf) {
            int col = n0 + wn + nf * 8 + 2 * t;
            float bb0 = bv[col] * bscale, bb1 = bv[col + 1] * bscale;
#pragma unroll
            for (int half = 0; half < 2; ++half) {
                int mrow = m0 + rl + half * 8;
                if (mrow >= cnt) continue;
                float v0 = acc[mf][nf][half * 2 + 0] + bb0;
                float v1 = acc[mf][nf][half * 2 + 1] + bb1;
                if (PHASE == 1) {
                    size_t o = (size_t)(base + mrow) * FDIM + col;
                    *(__half2*)&g_hmidh[o] =
                        __float22half2_rn(make_float2(gelu_exact(v0), gelu_exact(v1)));
                } else {
                    int slot = base + mrow;
                    int tok = g_slot_tok[slot];
                    float w = g_slot_w[slot];
                    red_v2(&out[(size_t)tok * HDIM + col], w * v0, w * v1);
                }
            }
        }
    }

    if (PHASE == 1) {
        // release hmid writes, then signal this CTA done for expert e
        __syncthreads();
        if (tid == 0) {
            __threadfence();
            atomicAdd(&g_done[e], 1);
        }
    }
}

// fused kernel: z in [0,6) -> phase 1 expert z (x = N-tile 0..23)
//               z in [6,12) -> phase 2 expert z-6 (x<12: ks = x/6, nx = x%6)
// bid order is z-slowest => all phase-1 CTAs dispatch before phase-2 CTAs;
// phase-2 spin-wait targets only lower-bid CTAs -> deadlock-free.
__global__ void __launch_bounds__(256, 2) moe_fused(const float* __restrict__ b1,
                                                    const float* __restrict__ b2,
                                                    float* __restrict__ out) {
    const int z = blockIdx.z;
    if (z < ENUM) {
        gemm_body<1, 1>(z, 0, blockIdx.x, blockIdx.y, b1, nullptr);
    } else {
        const int x = blockIdx.x;
        if (x >= 12) { GRID_DEP_WAIT(); return; }
        gemm_body<2, 2>(z - ENUM, x / 6, x % 6, blockIdx.y, b2, out);
    }
}

// ---------------- launch (PDL chain) ----------------
template <typename... Args>
static void launch_pdl(void (*k)(Args...), dim3 grid, dim3 block, size_t smem,
                       Args... args) {
    cudaLaunchAttribute attr[1];
    attr[0].id = cudaLaunchAttributeProgrammaticStreamSerialization;
    attr[0].val.programmaticStreamSerializationAllowed = 1;
    cudaLaunchConfig_t cfg = {};
    cfg.gridDim = grid;
    cfg.blockDim = block;
    cfg.dynamicSmemBytes = smem;
    cfg.attrs = attr;
    cfg.numAttrs = 1;
    cudaLaunchKernelEx(&cfg, k, args...);
}

extern "C" void kernel_launch(void* const* d_in, const int* in_sizes, int n_in,
                              void* d_out, int out_size) {
    const float* x  = (const float*)d_in[0];
    const float* gw = (const float*)d_in[1];
    const float* gb = (const float*)d_in[2];
    const float* w1 = (const float*)d_in[3];
    const float* b1 = (const float*)d_in[4];
    const float* w2 = (const float*)d_in[5];
    const float* b2 = (const float*)d_in[6];
    float* out = (float*)d_out;

    cudaFuncSetAttribute(moe_fused, cudaFuncAttributeMaxDynamicSharedMemorySize, SMEM_REQ);

    prep_w_k<<<dim3(FDIM / 32, HDIM / 32, 2 * ENUM), 256>>>(w1, w2);
    launch_pdl(gate_kernel, dim3(NTOK / 8), dim3(256), 0, x, gw, gb, out);
    launch_pdl(moe_fused, dim3(FDIM / 128, EBKT / 128, 2 * ENUM), dim3(256),
               (size_t)SMEM_REQ, b1, b2, out);
}